// round 3
// baseline (speedup 1.0000x reference)
#include <cuda_runtime.h>
#include <cstdint>

#define MAX_NODES 100000
#define MAX_EDGES 3200000
#define MAX_GRAPHS 512
#define HID 64

// Scratch (static device globals; 16B-aligned for float4 / red.v4 access)
__device__ __align__(16) float g_h  [MAX_NODES * HID];   // pre-agg features (x@W)
__device__ __align__(16) float g_o1 [MAX_NODES * HID];   // layer-1 output accum
__device__ __align__(16) float g_o2 [MAX_NODES * HID];   // layer-2 output accum
__device__ __align__(16) float g_dis[MAX_NODES];         // deg, then rsqrt(deg)
__device__ __align__(16) float g_cnt[MAX_GRAPHS];        // nodes per graph
__device__ int g_src  [MAX_EDGES];                       // normalized int32 indices
__device__ int g_dst  [MAX_EDGES];
__device__ int g_batch[MAX_NODES];
__device__ unsigned g_flags[2];                          // [0]=edge is32, [1]=batch is32

// ---------------------------------------------------------------------------
// Dtype probe: int64 data has zero high words; int32 tails are nonzero here.
// Only reads within the first `count` 32-bit words (safe for both dtypes).
__global__ void probe_kernel(const unsigned* __restrict__ ei_raw, int ei_count,
                             const unsigned* __restrict__ b_raw,  int b_count)
{
    if (blockIdx.x == 0 && threadIdx.x < 2) g_flags[threadIdx.x] = 0u;
    __syncthreads();
    int t = threadIdx.x;                       // 256 threads, 1 block
    unsigned acc0 = 0, acc1 = 0;
    for (int k = t; k < 512; k += 256) {
        int w0 = ei_count - 1 - 2 * k;         // odd-offset words from the tail
        if ((w0 & 1) == 0) w0 -= 1;
        if (w0 >= 1) acc0 |= ei_raw[w0];
        int w1 = b_count - 1 - 2 * k;
        if ((w1 & 1) == 0) w1 -= 1;
        if (w1 >= 1) acc1 |= b_raw[w1];
    }
    if (acc0) atomicOr(&g_flags[0], 1u);
    if (acc1) atomicOr(&g_flags[1], 1u);
}

// Normalize edge_index (interleaved [2,E]) and batch into int32 scratch.
__global__ void convert_kernel(const void* __restrict__ ei_raw, int e,
                               const void* __restrict__ b_raw,  int n)
{
    int i = blockIdx.x * blockDim.x + threadIdx.x;
    bool ei32 = (g_flags[0] != 0u);
    bool b32  = (g_flags[1] != 0u);
    if (i < e) {
        int s, d;
        if (ei32) {
            s = ((const int*)ei_raw)[i];
            d = ((const int*)ei_raw)[e + i];
        } else {
            s = (int)((const long long*)ei_raw)[i];
            d = (int)((const long long*)ei_raw)[e + i];
        }
        g_src[i] = min(max(s, 0), n - 1);
        g_dst[i] = min(max(d, 0), n - 1);
    }
    if (i < n) {
        int g = b32 ? ((const int*)b_raw)[i]
                    : (int)((const long long*)b_raw)[i];
        g_batch[i] = min(max(g, 0), MAX_GRAPHS - 1);
    }
}

// ---------------------------------------------------------------------------
__global__ void init_kernel(float* __restrict__ out, int n, int out_elems, int ng) {
    int i = blockIdx.x * blockDim.x + threadIdx.x;
    if (i < n) g_dis[i] = 1.0f;              // deg starts at 1 (self-loop)
    if (i < out_elems) out[i] = 0.0f;        // d_out is poisoned; zero it
    if (i < ng) g_cnt[i] = 0.0f;
}

__global__ void deg_kernel(int e) {
    int i = blockIdx.x * blockDim.x + threadIdx.x;
    if (i < e) atomicAdd(&g_dis[g_dst[i]], 1.0f);
}

__global__ void rsqrt_kernel(int n) {
    int i = blockIdx.x * blockDim.x + threadIdx.x;
    if (i < n) g_dis[i] = rsqrtf(g_dis[i]);
}

// ---------------------------------------------------------------------------
// GEMM: h = f(X) @ W  (f = optional relu), and  oinit = h * dis^2 + b.
// One thread per row. W (K x 64) broadcast from smem.
template<int K, bool RELU_IN>
__global__ void gcn_gemm(const float* __restrict__ X,
                         const float* __restrict__ W,
                         const float* __restrict__ bias,
                         float* __restrict__ hout,
                         float* __restrict__ oinit,
                         int n)
{
    __shared__ float4 Ws[K * 16];
    __shared__ float4 bs[16];
    for (int i = threadIdx.x; i < K * 16; i += blockDim.x)
        Ws[i] = reinterpret_cast<const float4*>(W)[i];
    if (threadIdx.x < 16)
        bs[threadIdx.x] = reinterpret_cast<const float4*>(bias)[threadIdx.x];
    __syncthreads();

    int r = blockIdx.x * blockDim.x + threadIdx.x;
    if (r >= n) return;

    float4 acc[16];
    #pragma unroll
    for (int c = 0; c < 16; ++c) acc[c] = make_float4(0.f, 0.f, 0.f, 0.f);

    const float4* xr = reinterpret_cast<const float4*>(X + (size_t)r * K);
    #pragma unroll 4
    for (int k4 = 0; k4 < K / 4; ++k4) {
        float4 xv = xr[k4];
        if (RELU_IN) {
            xv.x = fmaxf(xv.x, 0.f); xv.y = fmaxf(xv.y, 0.f);
            xv.z = fmaxf(xv.z, 0.f); xv.w = fmaxf(xv.w, 0.f);
        }
        const float4* w0 = &Ws[(k4 * 4 + 0) * 16];
        const float4* w1 = &Ws[(k4 * 4 + 1) * 16];
        const float4* w2 = &Ws[(k4 * 4 + 2) * 16];
        const float4* w3 = &Ws[(k4 * 4 + 3) * 16];
        #pragma unroll
        for (int c = 0; c < 16; ++c) {
            float4 a = acc[c];
            float4 wa = w0[c], wb = w1[c], wc = w2[c], wd = w3[c];
            a.x = fmaf(xv.x, wa.x, a.x); a.y = fmaf(xv.x, wa.y, a.y);
            a.z = fmaf(xv.x, wa.z, a.z); a.w = fmaf(xv.x, wa.w, a.w);
            a.x = fmaf(xv.y, wb.x, a.x); a.y = fmaf(xv.y, wb.y, a.y);
            a.z = fmaf(xv.y, wb.z, a.z); a.w = fmaf(xv.y, wb.w, a.w);
            a.x = fmaf(xv.z, wc.x, a.x); a.y = fmaf(xv.z, wc.y, a.y);
            a.z = fmaf(xv.z, wc.z, a.z); a.w = fmaf(xv.z, wc.w, a.w);
            a.x = fmaf(xv.w, wd.x, a.x); a.y = fmaf(xv.w, wd.y, a.y);
            a.z = fmaf(xv.w, wd.z, a.z); a.w = fmaf(xv.w, wd.w, a.w);
            acc[c] = a;
        }
    }

    float ds   = g_dis[r];
    float self = ds * ds;     // 1/deg  (self-loop norm)
    float4* hp = reinterpret_cast<float4*>(hout  + (size_t)r * HID);
    float4* op = reinterpret_cast<float4*>(oinit + (size_t)r * HID);
    #pragma unroll
    for (int c = 0; c < 16; ++c) {
        float4 h = acc[c];
        hp[c] = h;
        float4 b = bs[c];
        float4 o;
        o.x = fmaf(h.x, self, b.x); o.y = fmaf(h.y, self, b.y);
        o.z = fmaf(h.z, self, b.z); o.w = fmaf(h.w, self, b.w);
        op[c] = o;
    }
}

// ---------------------------------------------------------------------------
// Edge aggregation: out[dst] += h[src] * (dis[src]*dis[dst]).
// 16 threads per edge, each handles one float4 column chunk. Vector reduction
// (red.global.add.v4.f32, sm_90+) — 1/4 the atomic op count of scalar adds.
__global__ void agg_kernel(const float* __restrict__ h,
                           float* __restrict__ out,
                           int e)
{
    int idx = blockIdx.x * blockDim.x + threadIdx.x;
    if (idx >= e * 16) return;
    int ei = idx >> 4;
    int c  = idx & 15;
    int s = g_src[ei];
    int d = g_dst[ei];
    float nrm = g_dis[s] * g_dis[d];
    float4 v = reinterpret_cast<const float4*>(h)[s * 16 + c];
    float* p = out + (size_t)d * HID + c * 4;
    asm volatile("red.global.add.v4.f32 [%0], {%1, %2, %3, %4};"
                 :: "l"(p), "f"(v.x * nrm), "f"(v.y * nrm),
                    "f"(v.z * nrm), "f"(v.w * nrm)
                 : "memory");
}

// ---------------------------------------------------------------------------
// Pool: out[batch[i]] += relu(o2[i]);  cnt[batch[i]] += 1.
__global__ void pool_kernel(const float* __restrict__ o2,
                            float* __restrict__ out,
                            int n)
{
    int idx = blockIdx.x * blockDim.x + threadIdx.x;
    if (idx >= n * 16) return;
    int i = idx >> 4;
    int c = idx & 15;
    int g = g_batch[i];
    float4 v = reinterpret_cast<const float4*>(o2)[i * 16 + c];
    v.x = fmaxf(v.x, 0.f); v.y = fmaxf(v.y, 0.f);
    v.z = fmaxf(v.z, 0.f); v.w = fmaxf(v.w, 0.f);
    float* p = out + (size_t)g * HID + c * 4;
    asm volatile("red.global.add.v4.f32 [%0], {%1, %2, %3, %4};"
                 :: "l"(p), "f"(v.x), "f"(v.y), "f"(v.z), "f"(v.w)
                 : "memory");
    if (c == 0) atomicAdd(&g_cnt[g], 1.0f);
}

__global__ void div_kernel(float* __restrict__ out, int total) {
    int i = blockIdx.x * blockDim.x + threadIdx.x;
    if (i < total) out[i] = out[i] / fmaxf(g_cnt[i >> 6], 1.0f);
}

// ---------------------------------------------------------------------------
extern "C" void kernel_launch(void* const* d_in, const int* in_sizes, int n_in,
                              void* d_out, int out_size)
{
    // Identify inputs by element count (robust to metadata ordering):
    //   x: n*128 (12.8M)  edge_index: 2*E (6.4M)  batch: n (100k)
    //   W1: 8192  W2: 4096  b1,b2: 64 each (relative order preserved)
    const float* x  = nullptr;
    const void*  ei = nullptr;
    const void*  bt = nullptr;
    const float *W1 = nullptr, *W2 = nullptr, *b1 = nullptr, *b2 = nullptr;
    int n = 0, e = 0;

    long long maxsz = 0;
    for (int i = 0; i < n_in; ++i) if (in_sizes[i] > maxsz) maxsz = in_sizes[i];
    for (int i = 0; i < n_in; ++i) {
        if (in_sizes[i] == maxsz && !x) { x = (const float*)d_in[i]; n = (int)(maxsz / 128); }
    }
    for (int i = 0; i < n_in; ++i) {
        long long sz = in_sizes[i];
        const void* p = d_in[i];
        if (p == (const void*)x) continue;
        if (sz == (long long)n)      { bt = p; }
        else if (sz > (long long)n)  { ei = p; e = (int)(sz / 2); }
        else if (sz == 128 * 64)     { W1 = (const float*)p; }
        else if (sz == 64 * 64)      { W2 = (const float*)p; }
        else if (sz == 64)           { if (!b1) b1 = (const float*)p; else b2 = (const float*)p; }
    }

    float* out = (float*)d_out;
    const int ng = out_size / HID;     // 512

    float *ph, *po1, *po2;
    cudaGetSymbolAddress((void**)&ph,  g_h);
    cudaGetSymbolAddress((void**)&po1, g_o1);
    cudaGetSymbolAddress((void**)&po2, g_o2);

    const int T = 256;
    const int mx = (e > n ? e : n);

    // Detect index dtype and normalize to int32 scratch.
    probe_kernel  <<<1, 256>>>((const unsigned*)ei, 2 * e, (const unsigned*)bt, n);
    convert_kernel<<<(mx + T - 1) / T, T>>>(ei, e, bt, n);

    init_kernel <<<(n + T - 1) / T, T>>>(out, n, out_size, ng);
    deg_kernel  <<<(e + T - 1) / T, T>>>(e);
    rsqrt_kernel<<<(n + T - 1) / T, T>>>(n);

    // Layer 1: h = x@W1; o1 = h/deg + b1; o1 += scatter(h[src]*norm)
    gcn_gemm<128, false><<<(n + T - 1) / T, T>>>(x, W1, b1, ph, po1, n);
    agg_kernel<<<(e * 16 + T - 1) / T, T>>>(ph, po1, e);

    // Layer 2: h = relu(o1)@W2; o2 = h/deg + b2; o2 += scatter(h[src]*norm)
    gcn_gemm<64, true><<<(n + T - 1) / T, T>>>(po1, W2, b2, ph, po2, n);
    agg_kernel<<<(e * 16 + T - 1) / T, T>>>(ph, po2, e);

    // Global mean pool over relu(o2)
    pool_kernel<<<(n * 16 + T - 1) / T, T>>>(po2, out, n);
    div_kernel <<<(out_size + T - 1) / T, T>>>(out, out_size);
}

// round 4
// speedup vs baseline: 1.7252x; 1.7252x over previous
#include <cuda_runtime.h>
#include <cstdint>

#define MAX_NODES 100000
#define MAX_EDGES 3200000
#define MAX_GRAPHS 512
#define HID 64
#define SCAN_B 256

// Scratch (static device globals)
__device__ __align__(16) float g_h  [MAX_NODES * HID];   // h_pre = (f(X)@W) * dis
__device__ __align__(16) float g_o1 [MAX_NODES * HID];   // layer-1 final (relu'd)
__device__ __align__(16) float g_o2 [MAX_NODES * HID];   // layer-2 final (relu'd)
__device__ __align__(16) float g_dis[MAX_NODES];         // rsqrt(deg)
__device__ __align__(16) float g_cnt[MAX_GRAPHS];        // nodes per graph
__device__ int g_src   [MAX_EDGES];                      // normalized int32 indices
__device__ int g_dst   [MAX_EDGES];
__device__ int g_ssrc  [MAX_EDGES];                      // src sorted by dst (CSR)
__device__ int g_count [MAX_NODES];                      // in-degree (no self loop)
__device__ int g_rowst [MAX_NODES];                      // CSR row start
__device__ int g_cursor[MAX_NODES];                      // scatter cursor
__device__ int g_bsum  [(MAX_NODES + SCAN_B - 1) / SCAN_B];
__device__ int g_boff  [(MAX_NODES + SCAN_B - 1) / SCAN_B];
__device__ int g_batch [MAX_NODES];
__device__ unsigned g_flags[2];                          // dtype probe results

// ---------------------------------------------------------------------------
// Dtype probe: int64 data has zero high words; int32 tails are nonzero here.
__global__ void probe_kernel(const unsigned* __restrict__ ei_raw, int ei_count,
                             const unsigned* __restrict__ b_raw,  int b_count)
{
    if (threadIdx.x < 2) g_flags[threadIdx.x] = 0u;
    __syncthreads();
    unsigned acc0 = 0, acc1 = 0;
    for (int k = threadIdx.x; k < 512; k += 256) {
        int w0 = ei_count - 1 - 2 * k;
        if ((w0 & 1) == 0) w0 -= 1;
        if (w0 >= 1) acc0 |= ei_raw[w0];
        int w1 = b_count - 1 - 2 * k;
        if ((w1 & 1) == 0) w1 -= 1;
        if (w1 >= 1) acc1 |= b_raw[w1];
    }
    if (acc0) atomicOr(&g_flags[0], 1u);
    if (acc1) atomicOr(&g_flags[1], 1u);
}

__global__ void init_kernel(float* __restrict__ out, int n, int out_elems, int ng) {
    int i = blockIdx.x * blockDim.x + threadIdx.x;
    if (i < n) g_count[i] = 0;
    if (i < out_elems) out[i] = 0.0f;
    if (i < ng) g_cnt[i] = 0.0f;
}

// Normalize indices to int32 scratch + fused in-degree histogram.
__global__ void convert_kernel(const void* __restrict__ ei_raw, int e,
                               const void* __restrict__ b_raw,  int n)
{
    int i = blockIdx.x * blockDim.x + threadIdx.x;
    bool ei32 = (g_flags[0] != 0u);
    bool b32  = (g_flags[1] != 0u);
    if (i < e) {
        int s, d;
        if (ei32) {
            s = ((const int*)ei_raw)[i];
            d = ((const int*)ei_raw)[e + i];
        } else {
            s = (int)((const long long*)ei_raw)[i];
            d = (int)((const long long*)ei_raw)[e + i];
        }
        s = min(max(s, 0), n - 1);
        d = min(max(d, 0), n - 1);
        g_src[i] = s;
        g_dst[i] = d;
        atomicAdd(&g_count[d], 1);
    }
    if (i < n) {
        int g = b32 ? ((const int*)b_raw)[i]
                    : (int)((const long long*)b_raw)[i];
        g_batch[i] = min(max(g, 0), MAX_GRAPHS - 1);
    }
}

// ---------------------------------------------------------------------------
// 3-phase exclusive prefix scan over g_count -> g_rowst (and cursor copy).
__global__ void scan_a(int n) {                       // per-block sums
    __shared__ int s[SCAN_B];
    int i = blockIdx.x * SCAN_B + threadIdx.x;
    int v = (i < n) ? g_count[i] : 0;
    s[threadIdx.x] = v;
    __syncthreads();
    for (int off = 1; off < SCAN_B; off <<= 1) {
        int t = (threadIdx.x >= off) ? s[threadIdx.x - off] : 0;
        __syncthreads();
        s[threadIdx.x] += t;
        __syncthreads();
    }
    if (threadIdx.x == SCAN_B - 1) g_bsum[blockIdx.x] = s[SCAN_B - 1];
}

__global__ void scan_b(int nb) {                      // scan of block sums (1 block, 512 thr)
    __shared__ int s[512];
    int t = threadIdx.x;
    int v = (t < nb) ? g_bsum[t] : 0;
    s[t] = v;
    __syncthreads();
    for (int off = 1; off < 512; off <<= 1) {
        int u = (t >= off) ? s[t - off] : 0;
        __syncthreads();
        s[t] += u;
        __syncthreads();
    }
    if (t < nb) g_boff[t] = s[t] - v;                 // exclusive
}

__global__ void scan_c(int n) {                       // final row starts + cursors + dis
    __shared__ int s[SCAN_B];
    int i = blockIdx.x * SCAN_B + threadIdx.x;
    int v = (i < n) ? g_count[i] : 0;
    s[threadIdx.x] = v;
    __syncthreads();
    for (int off = 1; off < SCAN_B; off <<= 1) {
        int t = (threadIdx.x >= off) ? s[threadIdx.x - off] : 0;
        __syncthreads();
        s[threadIdx.x] += t;
        __syncthreads();
    }
    if (i < n) {
        int row = g_boff[blockIdx.x] + s[threadIdx.x] - v;  // exclusive
        g_rowst[i]  = row;
        g_cursor[i] = row;
        g_dis[i] = rsqrtf((float)v + 1.0f);           // deg incl. self-loop
    }
}

// Counting-sort scatter: sorted src list grouped by dst.
__global__ void scatter_kernel(int e) {
    int i = blockIdx.x * blockDim.x + threadIdx.x;
    if (i < e) {
        int d = g_dst[i];
        int pos = atomicAdd(&g_cursor[d], 1);
        g_ssrc[pos] = g_src[i];
    }
}

// ---------------------------------------------------------------------------
// GEMM: h_pre = (f(X) @ W) * dis[r].  One thread per row, W broadcast in smem.
template<int K, bool RELU_IN>
__global__ void gcn_gemm(const float* __restrict__ X,
                         const float* __restrict__ W,
                         float* __restrict__ hout,
                         int n)
{
    __shared__ float4 Ws[K * 16];
    for (int i = threadIdx.x; i < K * 16; i += blockDim.x)
        Ws[i] = reinterpret_cast<const float4*>(W)[i];
    __syncthreads();

    int r = blockIdx.x * blockDim.x + threadIdx.x;
    if (r >= n) return;

    float4 acc[16];
    #pragma unroll
    for (int c = 0; c < 16; ++c) acc[c] = make_float4(0.f, 0.f, 0.f, 0.f);

    const float4* xr = reinterpret_cast<const float4*>(X + (size_t)r * K);
    #pragma unroll 4
    for (int k4 = 0; k4 < K / 4; ++k4) {
        float4 xv = xr[k4];
        if (RELU_IN) {
            xv.x = fmaxf(xv.x, 0.f); xv.y = fmaxf(xv.y, 0.f);
            xv.z = fmaxf(xv.z, 0.f); xv.w = fmaxf(xv.w, 0.f);
        }
        const float4* w0 = &Ws[(k4 * 4 + 0) * 16];
        const float4* w1 = &Ws[(k4 * 4 + 1) * 16];
        const float4* w2 = &Ws[(k4 * 4 + 2) * 16];
        const float4* w3 = &Ws[(k4 * 4 + 3) * 16];
        #pragma unroll
        for (int c = 0; c < 16; ++c) {
            float4 a = acc[c];
            float4 wa = w0[c], wb = w1[c], wc = w2[c], wd = w3[c];
            a.x = fmaf(xv.x, wa.x, a.x); a.y = fmaf(xv.x, wa.y, a.y);
            a.z = fmaf(xv.x, wa.z, a.z); a.w = fmaf(xv.x, wa.w, a.w);
            a.x = fmaf(xv.y, wb.x, a.x); a.y = fmaf(xv.y, wb.y, a.y);
            a.z = fmaf(xv.y, wb.z, a.z); a.w = fmaf(xv.y, wb.w, a.w);
            a.x = fmaf(xv.z, wc.x, a.x); a.y = fmaf(xv.z, wc.y, a.y);
            a.z = fmaf(xv.z, wc.z, a.z); a.w = fmaf(xv.z, wc.w, a.w);
            a.x = fmaf(xv.w, wd.x, a.x); a.y = fmaf(xv.w, wd.y, a.y);
            a.z = fmaf(xv.w, wd.z, a.z); a.w = fmaf(xv.w, wd.w, a.w);
            acc[c] = a;
        }
    }

    float ds = g_dis[r];
    float4* hp = reinterpret_cast<float4*>(hout + (size_t)r * HID);
    #pragma unroll
    for (int c = 0; c < 16; ++c) {
        float4 h = acc[c];
        h.x *= ds; h.y *= ds; h.z *= ds; h.w *= ds;
        hp[c] = h;
    }
}

// ---------------------------------------------------------------------------
// CSR aggregation: one warp per dst node, lane owns 2 channels (float2).
//   out[d] = relu( (h_pre[d] + sum_{s in row(d)} h_pre[s]) * dis[d] + b )
__global__ void agg_csr(const float* __restrict__ h,
                        const float* __restrict__ bias,
                        float* __restrict__ out,
                        int n)
{
    int warp = (blockIdx.x * blockDim.x + threadIdx.x) >> 5;
    int lane = threadIdx.x & 31;
    if (warp >= n) return;

    const float2* hp = reinterpret_cast<const float2*>(h);
    float2 acc = hp[warp * 32 + lane];        // self term (h_pre[dst])
    int beg = g_rowst[warp];
    int end = beg + g_count[warp];

    int j = beg;
    for (; j + 1 < end; j += 2) {
        int s0 = g_ssrc[j];
        int s1 = g_ssrc[j + 1];
        float2 v0 = hp[s0 * 32 + lane];
        float2 v1 = hp[s1 * 32 + lane];
        acc.x += v0.x + v1.x;
        acc.y += v0.y + v1.y;
    }
    if (j < end) {
        int s = g_ssrc[j];
        float2 v = hp[s * 32 + lane];
        acc.x += v.x; acc.y += v.y;
    }

    float ds = g_dis[warp];
    float bx = __ldg(&bias[lane * 2]);
    float by = __ldg(&bias[lane * 2 + 1]);
    float2 o;
    o.x = fmaxf(fmaf(acc.x, ds, bx), 0.f);
    o.y = fmaxf(fmaf(acc.y, ds, by), 0.f);
    reinterpret_cast<float2*>(out)[warp * 32 + lane] = o;
}

// ---------------------------------------------------------------------------
// Pool: out[batch[i]] += o2[i] (already relu'd);  cnt[batch[i]] += 1.
__global__ void pool_kernel(const float* __restrict__ o2,
                            float* __restrict__ out,
                            int n)
{
    int idx = blockIdx.x * blockDim.x + threadIdx.x;
    if (idx >= n * 16) return;
    int i = idx >> 4;
    int c = idx & 15;
    int g = g_batch[i];
    float4 v = reinterpret_cast<const float4*>(o2)[i * 16 + c];
    float* p = out + (size_t)g * HID + c * 4;
    asm volatile("red.global.add.v4.f32 [%0], {%1, %2, %3, %4};"
                 :: "l"(p), "f"(v.x), "f"(v.y), "f"(v.z), "f"(v.w)
                 : "memory");
    if (c == 0) atomicAdd(&g_cnt[g], 1.0f);
}

__global__ void div_kernel(float* __restrict__ out, int total) {
    int i = blockIdx.x * blockDim.x + threadIdx.x;
    if (i < total) out[i] = out[i] / fmaxf(g_cnt[i >> 6], 1.0f);
}

// ---------------------------------------------------------------------------
extern "C" void kernel_launch(void* const* d_in, const int* in_sizes, int n_in,
                              void* d_out, int out_size)
{
    // Identify inputs by element count.
    const float* x  = nullptr;
    const void  *ei = nullptr, *bt = nullptr;
    const float *W1 = nullptr, *W2 = nullptr, *b1 = nullptr, *b2 = nullptr;
    int n = 0, e = 0;

    long long maxsz = 0;
    for (int i = 0; i < n_in; ++i) if (in_sizes[i] > maxsz) maxsz = in_sizes[i];
    for (int i = 0; i < n_in; ++i)
        if (in_sizes[i] == maxsz && !x) { x = (const float*)d_in[i]; n = (int)(maxsz / 128); }
    for (int i = 0; i < n_in; ++i) {
        long long sz = in_sizes[i];
        const void* p = d_in[i];
        if (p == (const void*)x) continue;
        if (sz == (long long)n)      { bt = p; }
        else if (sz > (long long)n)  { ei = p; e = (int)(sz / 2); }
        else if (sz == 128 * 64)     { W1 = (const float*)p; }
        else if (sz == 64 * 64)      { W2 = (const float*)p; }
        else if (sz == 64)           { if (!b1) b1 = (const float*)p; else b2 = (const float*)p; }
    }

    float* out = (float*)d_out;
    const int ng = out_size / HID;

    float *ph, *po1, *po2;
    cudaGetSymbolAddress((void**)&ph,  g_h);
    cudaGetSymbolAddress((void**)&po1, g_o1);
    cudaGetSymbolAddress((void**)&po2, g_o2);

    const int T = 256;
    const int mx = (e > n ? e : n);
    const int nb = (n + SCAN_B - 1) / SCAN_B;

    init_kernel   <<<(mx + T - 1) / T, T>>>(out, n, out_size, ng);
    probe_kernel  <<<1, 256>>>((const unsigned*)ei, 2 * e, (const unsigned*)bt, n);
    convert_kernel<<<(mx + T - 1) / T, T>>>(ei, e, bt, n);

    // CSR build: scan + scatter (also computes dis = rsqrt(deg+1))
    scan_a<<<nb, SCAN_B>>>(n);
    scan_b<<<1, 512>>>(nb);
    scan_c<<<nb, SCAN_B>>>(n);
    scatter_kernel<<<(e + T - 1) / T, T>>>(e);

    // Layer 1
    gcn_gemm<128, false><<<(n + T - 1) / T, T>>>(x, W1, ph, n);
    agg_csr<<<(n * 32 + T - 1) / T, T>>>(ph, b1, po1, n);

    // Layer 2 (o1 already relu'd)
    gcn_gemm<64, false><<<(n + T - 1) / T, T>>>(po1, W2, ph, n);
    agg_csr<<<(n * 32 + T - 1) / T, T>>>(ph, b2, po2, n);

    // Global mean pool
    pool_kernel<<<(n * 16 + T - 1) / T, T>>>(po2, out, n);
    div_kernel <<<(out_size + T - 1) / T, T>>>(out, out_size);
}